// round 1
// baseline (speedup 1.0000x reference)
#include <cuda_runtime.h>

// ---------------- problem constants ----------------
#define Ncst   8
#define Tcst   192
#define Hcst   1024
#define Dcst   128
#define TPcst  48
#define NBcst  384            // N * TP
#define Ecst   16384
#define EHcst  17408          // E + H (self loops)
#define OUTHALF 196608        // N * (TP*4) * D

// ---------------- device scratch (static, no allocs) ----------------
__device__ float g_U [(long)NBcst*Hcst*Dcst];   // 201 MB  : tv @ W1, folded
__device__ float g_Hb[(long)NBcst*Hcst*Dcst];   // 201 MB  : relu(A@U + b1)
__device__ float g_time[NBcst*Dcst];
__device__ float g_WW1[4*Dcst];
__device__ float g_bb1[Dcst];
__device__ int   g_cnt[Hcst];
__device__ float g_deg[Hcst];
__device__ int   g_rowptr[Hcst+1];
__device__ int   g_cursor[Hcst];
__device__ int   g_col[EHcst];
__device__ float g_coef[EHcst];
__device__ float g_partial[(long)NBcst*32*Dcst];
__device__ int   g_flags[3];   // [0]=x_mark is int64, [1]=edges, [2]=node_split

// read integer index from buffer that may be int32 or int64 (little-endian, small nonneg values)
__device__ __forceinline__ int gidx(const void* p, long i, int f64) {
    return f64 ? (int)((const long long*)p)[i] : ((const int*)p)[i];
}

// ---------------- dtype detection ----------------
// For int64 arrays of small nonneg values, all odd 32-bit words are zero.
// For the actual int32 data here, that is (astronomically) never true.
__global__ void k_detect(const void* xm, const void* ed, const void* ns) {
    __shared__ int nz[3];
    int t = threadIdx.x;
    if (t < 3) nz[t] = 0;
    __syncthreads();
    if (t < 192) {
        const void* bufs[3] = {xm, ed, ns};
        int which = t >> 6, j = t & 63;
        // word index 2j+1 <= 127, safely within the smallest buffer (node_split: 1024 words min)
        int w = ((const int*)bufs[which])[2*j+1];
        if (w != 0) atomicOr(&nz[which], 1);
    }
    __syncthreads();
    if (t < 3) g_flags[t] = nz[t] ? 0 : 1;
}

// ---------------- graph preprocessing ----------------
__global__ void k_init() {
    int v = blockIdx.x*blockDim.x + threadIdx.x;
    if (v < Hcst) g_cnt[v] = 1;   // self-loop
}
__global__ void k_count(const void* ed) {
    int i = blockIdx.x*blockDim.x + threadIdx.x;
    if (i < Ecst) {
        int d = gidx(ed, 2L*i+1, g_flags[1]);
        atomicAdd(&g_cnt[d], 1);
    }
}
__global__ void k_scan() {
    __shared__ int s[Hcst];
    int t = threadIdx.x;
    int c = g_cnt[t];
    s[t] = c;
    __syncthreads();
    for (int off = 1; off < Hcst; off <<= 1) {
        int v = (t >= off) ? s[t-off] : 0;
        __syncthreads();
        s[t] += v;
        __syncthreads();
    }
    g_rowptr[t] = s[t] - c;
    g_cursor[t] = s[t] - c;
    g_deg[t]    = (float)c;
    if (t == Hcst-1) g_rowptr[Hcst] = s[t];
}
__global__ void k_fill(const void* ed) {
    int i = blockIdx.x*blockDim.x + threadIdx.x;
    if (i >= EHcst) return;
    int s, d;
    if (i < Ecst) {
        int f = g_flags[1];
        s = gidx(ed, 2L*i,   f);
        d = gidx(ed, 2L*i+1, f);
    } else {
        s = d = i - Ecst;
    }
    int pos = atomicAdd(&g_cursor[d], 1);
    g_col[pos]  = s;
    g_coef[pos] = rsqrtf(g_deg[s]*g_deg[d]);
}

// ---------------- fold W1 into the rank-4 time conv: WW1 = Wt @ W1, bb1 = tb @ W1 ----
__global__ void k_ww1(const float* tw, const float* tb, const float* W1) {
    int t = threadIdx.x;
    int k = t >> 7, e = t & 127;
    float acc = 0.f;
    for (int d = 0; d < Dcst; d++) acc += tw[d*4 + k] * W1[d*Dcst + e];
    g_WW1[k*Dcst + e] = acc;
    if (t < Dcst) {
        float b = 0.f;
        for (int d = 0; d < Dcst; d++) b += tb[d] * W1[d*Dcst + t];
        g_bb1[t] = b;
    }
}

// ---------------- time embedding path (exact fp32) + write time_rep half of output ----
__global__ void k_time(const void* xm, const float* hemb, const float* wemb,
                       const float* tcw, const float* tcb, float* out) {
    __shared__ float es[4][Dcst];
    int b = blockIdx.x, tid = threadIdx.x;
    int n = b / TPcst, t = b % TPcst;
    int fm = g_flags[0];
    for (int idx = tid; idx < 4*Dcst; idx += 128) {
        int k = idx >> 7, c = idx & 127;
        long base = ((long)(n*Tcst + t*4 + k)) * 2;
        int ih = gidx(xm, base + 1, fm);
        int iw = gidx(xm, base + 0, fm);
        es[k][c] = hemb[ih*Dcst + c] + wemb[iw*Dcst + c];
    }
    __syncthreads();
    int d = tid;
    float acc = tcb[d];
    const float4* w4 = (const float4*)(tcw + (long)d*Dcst*4);
    #pragma unroll 4
    for (int c = 0; c < Dcst; c++) {
        float4 w = w4[c];
        acc += es[0][c]*w.x + es[1][c]*w.y + es[2][c]*w.z + es[3][c]*w.w;
    }
    g_time[b*Dcst + d] = acc;
    #pragma unroll
    for (int g = 0; g < 4; g++)
        out[OUTHALF + ((long)(n*192 + t*4 + g))*Dcst + d] = acc;
}

// ---------------- U = X4 @ WW1 + bb1 (GEMM1 collapsed) ----------------
__global__ void __launch_bounds__(128) k_U(const float* x) {
    __shared__ float sw[4*Dcst];
    __shared__ float sb[Dcst];
    int tid = threadIdx.x;
    #pragma unroll
    for (int i = tid; i < 4*Dcst; i += 128) sw[i] = g_WW1[i];
    sb[tid] = g_bb1[tid];
    __syncthreads();
    long row0 = (long)blockIdx.x * 8;
    #pragma unroll
    for (int r = 0; r < 8; r++) {
        long row = row0 + r;
        int b = (int)(row >> 10), h = (int)(row & 1023);
        int n = b / TPcst, t = b % TPcst;
        const float* xp = x + ((long)(n*Tcst + t*4))*Hcst + h;
        float x0 = xp[0], x1 = xp[Hcst], x2 = xp[2*Hcst], x3 = xp[3*Hcst];
        g_U[row*Dcst + tid] = sb[tid] + x0*sw[tid] + x1*sw[128+tid]
                                      + x2*sw[256+tid] + x3*sw[384+tid];
    }
}

// ---------------- propagate 1: Hb = relu(A @ U + b1) ----------------
__global__ void __launch_bounds__(128) k_g1(const float* b1) {
    int v = blockIdx.x, b = blockIdx.y, d = threadIdx.x;
    int s0 = g_rowptr[v], s1 = g_rowptr[v+1];
    const float* Ub = g_U + (long)b*Hcst*Dcst;
    float acc = b1[d];
    int i = s0;
    for (; i + 4 <= s1; i += 4) {
        int   c0 = g_col[i],   c1 = g_col[i+1],  c2 = g_col[i+2],  c3 = g_col[i+3];
        float w0 = g_coef[i],  w1 = g_coef[i+1], w2 = g_coef[i+2], w3 = g_coef[i+3];
        acc += w0*Ub[c0*Dcst+d] + w1*Ub[c1*Dcst+d] + w2*Ub[c2*Dcst+d] + w3*Ub[c3*Dcst+d];
    }
    for (; i < s1; i++) acc += g_coef[i]*Ub[g_col[i]*Dcst+d];
    g_Hb[(long)b*Hcst*Dcst + (long)v*Dcst + d] = fmaxf(acc, 0.f);
}

// ---------------- propagate 2 fused with group partial sums ----------------
__global__ void __launch_bounds__(128) k_g2(const void* ns) {
    int gx = blockIdx.x;              // g = gx>>3, chunk = gx&7 (32 nodes each)
    int b = blockIdx.y, d = threadIdx.x;
    int g = gx >> 3, ch = gx & 7;
    int fn = g_flags[2];
    const float* Hb = g_Hb + (long)b*Hcst*Dcst;
    float acc = 0.f;
    for (int j = 0; j < 32; j++) {
        int v = gidx(ns, (long)g*256 + ch*32 + j, fn);
        int s0 = g_rowptr[v], s1 = g_rowptr[v+1];
        int i = s0;
        for (; i + 4 <= s1; i += 4) {
            int   c0 = g_col[i],   c1 = g_col[i+1],  c2 = g_col[i+2],  c3 = g_col[i+3];
            float w0 = g_coef[i],  w1 = g_coef[i+1], w2 = g_coef[i+2], w3 = g_coef[i+3];
            acc += w0*Hb[c0*Dcst+d] + w1*Hb[c1*Dcst+d] + w2*Hb[c2*Dcst+d] + w3*Hb[c3*Dcst+d];
        }
        for (; i < s1; i++) acc += g_coef[i]*Hb[g_col[i]*Dcst+d];
    }
    g_partial[((long)b*32 + gx)*Dcst + d] = acc;
}

// ---------------- final: out = GM @ W2 + b2 + time_rep ----------------
__global__ void k_out(const float* W2, const float* b2, float* out) {
    __shared__ float gm[Dcst];
    int g = blockIdx.x, b = blockIdx.y, d = threadIdx.x;
    float s = 0.f;
    #pragma unroll
    for (int ch = 0; ch < 8; ch++)
        s += g_partial[((long)b*32 + g*8 + ch)*Dcst + d];
    gm[d] = s * (1.f/256.f);
    __syncthreads();
    float acc = b2[d] + g_time[b*Dcst + d];
    #pragma unroll 4
    for (int c = 0; c < Dcst; c++) acc += gm[c]*W2[c*Dcst + d];
    int n = b / TPcst, t = b % TPcst;
    out[((long)(n*192 + t*4 + g))*Dcst + d] = acc;
}

// ---------------- launch ----------------
extern "C" void kernel_launch(void* const* d_in, const int* in_sizes, int n_in,
                              void* d_out, int out_size) {
    const float* x    = (const float*)d_in[0];
    const void*  xm   = d_in[1];
    const void*  ed   = d_in[2];
    const void*  ns   = d_in[3];
    const float* hemb = (const float*)d_in[4];
    const float* wemb = (const float*)d_in[5];
    const float* tcw  = (const float*)d_in[6];
    const float* tcb  = (const float*)d_in[7];
    const float* tvw  = (const float*)d_in[8];
    const float* tvb  = (const float*)d_in[9];
    const float* W1   = (const float*)d_in[10];
    const float* b1   = (const float*)d_in[11];
    const float* W2   = (const float*)d_in[12];
    const float* b2   = (const float*)d_in[13];
    float* out = (float*)d_out;

    k_detect<<<1, 192>>>(xm, ed, ns);
    k_init  <<<4, 256>>>();
    k_count <<<64, 256>>>(ed);
    k_scan  <<<1, 1024>>>();
    k_fill  <<<68, 256>>>(ed);
    k_ww1   <<<1, 512>>>(tvw, tvb, W1);
    k_time  <<<NBcst, 128>>>(xm, hemb, wemb, tcw, tcb, out);
    k_U     <<<(NBcst*Hcst)/8, 128>>>(x);
    { dim3 gr(Hcst, NBcst); k_g1<<<gr, 128>>>(b1); }
    { dim3 gr(32,   NBcst); k_g2<<<gr, 128>>>(ns); }
    { dim3 gr(4,    NBcst); k_out<<<gr, 128>>>(W2, b2, out); }
}

// round 2
// speedup vs baseline: 7.5394x; 7.5394x over previous
#include <cuda_runtime.h>

// ---------------- problem constants ----------------
#define Ncst   8
#define Tcst   192
#define Hcst   1024
#define Dcst   128
#define TPcst  48
#define NBcst  384            // N * TP
#define Ecst   16384
#define EHcst  17408          // E + H (self loops)
#define OUTHALF 196608        // N * (TP*4) * D

// ---------------- device scratch (static, no allocs) ----------------
__device__ float4 g_X4t[(long)NBcst*Hcst];      // 6.3 MB : per-(b,node) conv taps
__device__ float4 g_Y  [(long)NBcst*Hcst];      // 6.3 MB : A @ X4
__device__ float  g_time[NBcst*Dcst];
__device__ float  g_WW1[4*Dcst];
__device__ float  g_bb1[Dcst];
__device__ int    g_cnt[Hcst];
__device__ float  g_deg[Hcst];
__device__ int    g_rowptr[Hcst+1];
__device__ int    g_cursor[Hcst];
__device__ int    g_col[EHcst];
__device__ float  g_coef[EHcst];
__device__ float  g_rowsum[Hcst];
__device__ float  g_S[4*Hcst];                  // S_g[u] = (1/256) sum_{v in g} A[v,u]
__device__ int    g_invgrp[Hcst];
__device__ int    g_flags[3];   // [0]=x_mark is int64, [1]=edges, [2]=node_split

__device__ __forceinline__ int gidx(const void* p, long i, int f64) {
    return f64 ? (int)((const long long*)p)[i] : ((const int*)p)[i];
}

// ---------------- dtype detection (int64 arrays of small values have zero odd words) ----
__global__ void k_detect(const void* xm, const void* ed, const void* ns) {
    __shared__ int nz[3];
    int t = threadIdx.x;
    if (t < 3) nz[t] = 0;
    __syncthreads();
    if (t < 192) {
        const void* bufs[3] = {xm, ed, ns};
        int which = t >> 6, j = t & 63;
        int w = ((const int*)bufs[which])[2*j+1];
        if (w != 0) atomicOr(&nz[which], 1);
    }
    __syncthreads();
    if (t < 3) g_flags[t] = nz[t] ? 0 : 1;
}

// ---------------- graph preprocessing ----------------
__global__ void k_init() {
    int i = blockIdx.x*blockDim.x + threadIdx.x;
    if (i < Hcst) { g_cnt[i] = 1; g_rowsum[i] = 0.f; }
    if (i < 4*Hcst) g_S[i] = 0.f;
}
__global__ void k_count(const void* ed) {
    int i = blockIdx.x*blockDim.x + threadIdx.x;
    if (i < Ecst) atomicAdd(&g_cnt[gidx(ed, 2L*i+1, g_flags[1])], 1);
}
__global__ void k_scan() {
    __shared__ int s[Hcst];
    int t = threadIdx.x;
    int c = g_cnt[t];
    s[t] = c;
    __syncthreads();
    for (int off = 1; off < Hcst; off <<= 1) {
        int v = (t >= off) ? s[t-off] : 0;
        __syncthreads();
        s[t] += v;
        __syncthreads();
    }
    g_rowptr[t] = s[t] - c;
    g_cursor[t] = s[t] - c;
    g_deg[t]    = (float)c;
    if (t == Hcst-1) g_rowptr[Hcst] = s[t];
}
__global__ void k_invgrp(const void* ns) {
    int i = blockIdx.x*blockDim.x + threadIdx.x;
    if (i < Hcst) g_invgrp[gidx(ns, i, g_flags[2])] = i >> 8;
}
// fill CSR + rowsum + S in one pass
__global__ void k_fill(const void* ed) {
    int i = blockIdx.x*blockDim.x + threadIdx.x;
    if (i >= EHcst) return;
    int s, d;
    if (i < Ecst) {
        int f = g_flags[1];
        s = gidx(ed, 2L*i,   f);
        d = gidx(ed, 2L*i+1, f);
    } else {
        s = d = i - Ecst;
    }
    float w = rsqrtf(g_deg[s]*g_deg[d]);
    int pos = atomicAdd(&g_cursor[d], 1);
    g_col[pos]  = s;
    g_coef[pos] = w;
    atomicAdd(&g_rowsum[d], w);
    atomicAdd(&g_S[g_invgrp[d]*Hcst + s], w * (1.f/256.f));
}

// ---------------- fold W1 into the rank-4 time conv ----------------
__global__ void k_ww1(const float* tw, const float* tb, const float* W1) {
    int t = threadIdx.x;
    int k = t >> 7, e = t & 127;
    float acc = 0.f;
    for (int d = 0; d < Dcst; d++) acc += tw[d*4 + k] * W1[d*Dcst + e];
    g_WW1[k*Dcst + e] = acc;
    if (t < Dcst) {
        float b = 0.f;
        for (int d = 0; d < Dcst; d++) b += tb[d] * W1[d*Dcst + t];
        g_bb1[t] = b;
    }
}

// ---------------- time embedding path (exact) + time_rep half of output ----------------
__global__ void k_time(const void* xm, const float* hemb, const float* wemb,
                       const float* tcw, const float* tcb, float* out) {
    __shared__ float es[4][Dcst];
    int b = blockIdx.x, tid = threadIdx.x;
    int n = b / TPcst, t = b % TPcst;
    int fm = g_flags[0];
    for (int idx = tid; idx < 4*Dcst; idx += 128) {
        int k = idx >> 7, c = idx & 127;
        long base = ((long)(n*Tcst + t*4 + k)) * 2;
        int ih = gidx(xm, base + 1, fm);
        int iw = gidx(xm, base + 0, fm);
        es[k][c] = hemb[ih*Dcst + c] + wemb[iw*Dcst + c];
    }
    __syncthreads();
    int d = tid;
    float acc = tcb[d];
    const float4* w4 = (const float4*)(tcw + (long)d*Dcst*4);
    #pragma unroll 4
    for (int c = 0; c < Dcst; c++) {
        float4 w = w4[c];
        acc += es[0][c]*w.x + es[1][c]*w.y + es[2][c]*w.z + es[3][c]*w.w;
    }
    g_time[b*Dcst + d] = acc;
    #pragma unroll
    for (int g = 0; g < 4; g++)
        out[OUTHALF + ((long)(n*192 + t*4 + g))*Dcst + d] = acc;
}

// ---------------- transpose x into per-(b,node) float4 taps ----------------
__global__ void k_x4t(const float* x) {
    long i = (long)blockIdx.x*256 + threadIdx.x;   // over NB*H
    int b = (int)(i >> 10), u = (int)(i & 1023);
    int n = b / TPcst, t = b % TPcst;
    long base = ((long)(n*Tcst + t*4))*Hcst + u;
    g_X4t[i] = make_float4(x[base], x[base+Hcst], x[base+2*Hcst], x[base+3*Hcst]);
}

// ---------------- Y = A @ X4 : the only gather left (4 floats per neighbor) ----------------
__global__ void __launch_bounds__(256) k_y() {
    long i = (long)blockIdx.x*256 + threadIdx.x;   // over NB*H
    int b = (int)(i >> 10), v = (int)(i & 1023);
    const float4* Xb = g_X4t + (long)b*Hcst;
    int s0 = g_rowptr[v], s1 = g_rowptr[v+1];
    float ax=0.f, ay=0.f, az=0.f, aw=0.f;
    for (int j = s0; j < s1; j++) {
        float w = g_coef[j];
        float4 xv = Xb[g_col[j]];
        ax += w*xv.x; ay += w*xv.y; az += w*xv.z; aw += w*xv.w;
    }
    g_Y[i] = make_float4(ax, ay, az, aw);
}

// ---------------- fused: h on-the-fly, group sums, @W2, + time_rep ----------------
__global__ void __launch_bounds__(128) k_tok(const float* b1, const float* W2,
                                             const float* b2, float* out) {
    __shared__ float4 sY[Hcst];        // 16 KB
    __shared__ float  sS[4][Hcst];     // 16 KB
    __shared__ float  sRS[Hcst];       // 4 KB
    __shared__ float  sAcc[4][Dcst];   // 2 KB
    int b = blockIdx.x, d = threadIdx.x;
    for (int i = d; i < Hcst; i += 128) {
        sY[i]  = g_Y[(long)b*Hcst + i];
        sRS[i] = g_rowsum[i];
        #pragma unroll
        for (int g = 0; g < 4; g++) sS[g][i] = g_S[g*Hcst + i];
    }
    __syncthreads();
    float w0 = g_WW1[d], w1 = g_WW1[128+d], w2 = g_WW1[256+d], w3 = g_WW1[384+d];
    float bb = g_bb1[d], bd = b1[d];
    float a0=0.f, a1=0.f, a2=0.f, a3=0.f;
    #pragma unroll 4
    for (int v = 0; v < Hcst; v++) {
        float4 y = sY[v];
        float hb = fmaxf(y.x*w0 + y.y*w1 + y.z*w2 + y.w*w3 + sRS[v]*bb + bd, 0.f);
        a0 += sS[0][v]*hb;
        a1 += sS[1][v]*hb;
        a2 += sS[2][v]*hb;
        a3 += sS[3][v]*hb;
    }
    sAcc[0][d] = a0; sAcc[1][d] = a1; sAcc[2][d] = a2; sAcc[3][d] = a3;
    __syncthreads();
    float tr = g_time[b*Dcst + d] + b2[d];
    float o0 = tr, o1 = tr, o2 = tr, o3 = tr;
    #pragma unroll 4
    for (int dd = 0; dd < Dcst; dd++) {
        float w = W2[dd*Dcst + d];
        o0 += sAcc[0][dd]*w;
        o1 += sAcc[1][dd]*w;
        o2 += sAcc[2][dd]*w;
        o3 += sAcc[3][dd]*w;
    }
    int n = b / TPcst, t = b % TPcst;
    long base = ((long)(n*192 + t*4))*Dcst + d;
    out[base]          = o0;
    out[base +   Dcst] = o1;
    out[base + 2*Dcst] = o2;
    out[base + 3*Dcst] = o3;
}

// ---------------- launch ----------------
extern "C" void kernel_launch(void* const* d_in, const int* in_sizes, int n_in,
                              void* d_out, int out_size) {
    const float* x    = (const float*)d_in[0];
    const void*  xm   = d_in[1];
    const void*  ed   = d_in[2];
    const void*  ns   = d_in[3];
    const float* hemb = (const float*)d_in[4];
    const float* wemb = (const float*)d_in[5];
    const float* tcw  = (const float*)d_in[6];
    const float* tcb  = (const float*)d_in[7];
    const float* tvw  = (const float*)d_in[8];
    const float* tvb  = (const float*)d_in[9];
    const float* W1   = (const float*)d_in[10];
    const float* b1   = (const float*)d_in[11];
    const float* W2   = (const float*)d_in[12];
    const float* b2   = (const float*)d_in[13];
    float* out = (float*)d_out;

    k_detect<<<1, 192>>>(xm, ed, ns);
    k_init  <<<16, 256>>>();
    k_count <<<64, 256>>>(ed);
    k_scan  <<<1, 1024>>>();
    k_invgrp<<<4, 256>>>(ns);
    k_fill  <<<68, 256>>>(ed);
    k_ww1   <<<1, 512>>>(tvw, tvb, W1);
    k_time  <<<NBcst, 128>>>(xm, hemb, wemb, tcw, tcb, out);
    k_x4t   <<<(NBcst*Hcst)/256, 256>>>(x);
    k_y     <<<(NBcst*Hcst)/256, 256>>>();
    k_tok   <<<NBcst, 128>>>(b1, W2, b2, out);
}

// round 3
// speedup vs baseline: 8.9646x; 1.1890x over previous
#include <cuda_runtime.h>
#include <cuda_bf16.h>

#define Hcst   1024
#define Dcst   128
#define TPcst  48
#define NBcst  384
#define Ecst   16384
#define EHcst  17408
#define OUTHALF 196608

typedef unsigned long long u64;

// ---------------- device scratch ----------------
__device__ float4 g_X4t[NBcst*Hcst];     // 6.3 MB
__device__ int    g_rowptr[Hcst+1];
__device__ int    g_cursor[Hcst];
__device__ float  g_deg[Hcst];
__device__ unsigned g_pk[EHcst];         // (bf16 coef)<<16 | u16 col
__device__ float  g_rowsum[Hcst];
__device__ float  g_S[4*Hcst];
__device__ int    g_invgrp[Hcst];
__device__ float  g_WW1[4*Dcst];
__device__ float  g_bb1[Dcst];

// ---------------- f32x2 helpers ----------------
__device__ __forceinline__ u64 pk2(float lo, float hi) {
    u64 r; asm("mov.b64 %0,{%1,%2};" : "=l"(r) : "f"(lo), "f"(hi)); return r;
}
__device__ __forceinline__ void upk2(u64 v, float& lo, float& hi) {
    asm("mov.b64 {%0,%1},%2;" : "=f"(lo), "=f"(hi) : "l"(v));
}
__device__ __forceinline__ u64 fma2(u64 a, u64 b, u64 c) {
    u64 d; asm("fma.rn.f32x2 %0,%1,%2,%3;" : "=l"(d) : "l"(a), "l"(b), "l"(c)); return d;
}

// int64-vs-int32 detection: for int64 buffers of small nonneg values all odd
// 32-bit words are zero; for the real int32 data that never happens (64 samples).
__device__ __forceinline__ int detect_i64(const void* p, int tid, int* sflag) {
    if (tid == 0) *sflag = 1;
    __syncthreads();
    if (tid < 64) { if (((const int*)p)[2*tid+1] != 0) atomicAnd(sflag, 0); }
    __syncthreads();
    return *sflag;
}

// ================= K_A : all graph prep that fits before fill =================
__global__ void kA(const void* ed, const void* ns,
                   const float* tw, const float* tb, const float* W1) {
    __shared__ int sflag;
    __shared__ int cnt[Hcst];
    __shared__ int wsum[32];
    int t = threadIdx.x;
    if (blockIdx.x == 0) {
        int f = detect_i64(ed, t, &sflag);
        cnt[t] = 1;                      // self loop
        __syncthreads();
        for (int i = t; i < Ecst; i += 1024) {
            int d = f ? (int)((const long long*)ed)[2L*i+1] : ((const int*)ed)[2*i+1];
            atomicAdd(&cnt[d], 1);
        }
        __syncthreads();
        int c = cnt[t];
        int lane = t & 31, wid = t >> 5;
        int v = c;
        #pragma unroll
        for (int o = 1; o < 32; o <<= 1) { int uu = __shfl_up_sync(~0u, v, o); if (lane >= o) v += uu; }
        if (lane == 31) wsum[wid] = v;
        __syncthreads();
        if (wid == 0) {
            int w = wsum[lane];
            #pragma unroll
            for (int o = 1; o < 32; o <<= 1) { int uu = __shfl_up_sync(~0u, w, o); if (lane >= o) w += uu; }
            wsum[lane] = w;
        }
        __syncthreads();
        int incl = v + (wid > 0 ? wsum[wid-1] : 0);
        g_rowptr[t] = incl - c;
        g_cursor[t] = incl - c;
        g_deg[t]    = (float)c;
        if (t == 1023) g_rowptr[Hcst] = incl;
    } else if (blockIdx.x == 1) {
        int f = detect_i64(ns, t, &sflag);
        int v = f ? (int)((const long long*)ns)[t] : ((const int*)ns)[t];
        g_invgrp[v] = t >> 8;
    } else if (blockIdx.x == 2) {
        if (t < 512) {
            int k = t >> 7, e = t & 127;
            float acc = 0.f;
            for (int d = 0; d < Dcst; d++) acc += tw[d*4 + k] * W1[d*Dcst + e];
            g_WW1[k*Dcst + e] = acc;
        }
        if (t < 128) {
            float bsum = 0.f;
            for (int d = 0; d < Dcst; d++) bsum += tb[d] * W1[d*Dcst + t];
            g_bb1[t] = bsum;
        }
    } else {
        for (int i = t; i < 4*Hcst; i += 1024) g_S[i] = 0.f;
        if (t < Hcst) g_rowsum[t] = 0.f;
    }
}

// ================= K_B : CSR fill + X4 transpose =================
__global__ void kB(const void* ed, const float* x) {
    int t = threadIdx.x;
    if (blockIdx.x < 68) {
        __shared__ int sflag;
        int f = detect_i64(ed, t, &sflag);
        int i = blockIdx.x*256 + t;
        if (i < EHcst) {
            int s, d;
            if (i < Ecst) {
                if (f) { s = (int)((const long long*)ed)[2L*i]; d = (int)((const long long*)ed)[2L*i+1]; }
                else   { s = ((const int*)ed)[2*i];             d = ((const int*)ed)[2*i+1]; }
            } else s = d = i - Ecst;
            float w = rsqrtf(g_deg[s]*g_deg[d]);
            int pos = atomicAdd(&g_cursor[d], 1);
            __nv_bfloat16 h = __float2bfloat16(w);
            unsigned cb = (unsigned)__bfloat16_as_ushort(h);
            g_pk[pos] = (unsigned)s | (cb << 16);
            atomicAdd(&g_rowsum[d], w);
            atomicAdd(&g_S[g_invgrp[d]*Hcst + s], w * (1.f/256.f));
        }
    } else {
        int b = blockIdx.x - 68;
        int n = b / TPcst, tp = b % TPcst;
        const float4* xr = (const float4*)(x + ((long)(n*192 + tp*4))*Hcst);
        float4 r0 = xr[t], r1 = xr[256+t], r2 = xr[512+t], r3 = xr[768+t];
        float4* dst = g_X4t + (long)b*Hcst + t*4;
        dst[0] = make_float4(r0.x, r1.x, r2.x, r3.x);
        dst[1] = make_float4(r0.y, r1.y, r2.y, r3.y);
        dst[2] = make_float4(r0.z, r1.z, r2.z, r3.z);
        dst[3] = make_float4(r0.w, r1.w, r2.w, r3.w);
    }
}

// ================= K_C : per-b mega kernel =================
__global__ void __launch_bounds__(256, 3) kC(const void* xm,
        const float* hemb, const float* wemb, const float* tcw, const float* tcb,
        const float* b1, const float* W2, const float* b2, float* out) {
    __shared__ ulonglong2 sYA[512];             // (Y0 pair, Y1 pair) per v-pair
    __shared__ ulonglong2 sYB[512];             // (Y2 pair, Y3 pair)
    __shared__ ulonglong2 sSI[1024];            // per v: (pk(S0,S1), pk(S2,S3))
    __shared__ u64 sRSp[512];                   // rowsum pairs
    __shared__ u64 sAcc[256][4];
    __shared__ union { float es[4][128]; ulonglong2 gm[128]; } sU;
    __shared__ int sflag;

    int t = threadIdx.x, b = blockIdx.x;
    int n = b / TPcst, tp = b % TPcst;

    // ---- flags + S/rowsum interleave ----
    if (t == 0) sflag = 1;
    __syncthreads();
    if (t < 64) { if (((const int*)xm)[2*t+1] != 0) atomicAnd(&sflag, 0); }
    for (int v = t; v < Hcst; v += 256) {
        ulonglong2 e;
        e.x = pk2(g_S[v],        g_S[Hcst+v]);
        e.y = pk2(g_S[2*Hcst+v], g_S[3*Hcst+v]);
        sSI[v] = e;
    }
    for (int vp = t; vp < 512; vp += 256)
        sRSp[vp] = pk2(g_rowsum[2*vp], g_rowsum[2*vp+1]);
    __syncthreads();
    int fm = sflag;

    // ---- time embedding ----
    for (int idx = t; idx < 512; idx += 256) {
        int k = idx >> 7, c = idx & 127;
        long base = ((long)(n*192 + tp*4 + k))*2;
        int ih, iw;
        if (fm) { ih = (int)((const long long*)xm)[base+1]; iw = (int)((const long long*)xm)[base]; }
        else    { ih = ((const int*)xm)[base+1];             iw = ((const int*)xm)[base]; }
        sU.es[k][c] = hemb[ih*Dcst + c] + wemb[iw*Dcst + c];
    }
    __syncthreads();
    float tr = 0.f;
    if (t < 128) {
        int d = t;
        float acc = tcb[d];
        const float4* w4 = (const float4*)(tcw + (long)d*512);
        #pragma unroll 4
        for (int c = 0; c < 128; c++) {
            float4 w = w4[c];
            acc += sU.es[0][c]*w.x + sU.es[1][c]*w.y + sU.es[2][c]*w.z + sU.es[3][c]*w.w;
        }
        tr = acc;
        long ob = OUTHALF + ((long)(n*192 + tp*4))*Dcst + d;
        out[ob] = acc; out[ob+128] = acc; out[ob+256] = acc; out[ob+384] = acc;
    }

    // ---- gather: Y = A @ X4 (per v-pair, store packed pairs) ----
    const float4* __restrict__ Xb = g_X4t + (long)b*Hcst;
    #pragma unroll
    for (int rep = 0; rep < 2; rep++) {
        int vp = t + rep*256;
        float y[2][4];
        #pragma unroll
        for (int e = 0; e < 2; e++) {
            int v = 2*vp + e;
            int j0 = g_rowptr[v], j1 = g_rowptr[v+1];
            float a0=0.f, a1=0.f, a2=0.f, a3=0.f;
            for (int j = j0; j < j1; j++) {
                unsigned p = __ldg(&g_pk[j]);
                float w = __uint_as_float(p & 0xFFFF0000u);
                float4 xv = __ldg(&Xb[p & 0xFFFFu]);
                a0 += w*xv.x; a1 += w*xv.y; a2 += w*xv.z; a3 += w*xv.w;
            }
            y[e][0]=a0; y[e][1]=a1; y[e][2]=a2; y[e][3]=a3;
        }
        ulonglong2 ea, eb;
        ea.x = pk2(y[0][0], y[1][0]); ea.y = pk2(y[0][1], y[1][1]);
        eb.x = pk2(y[0][2], y[1][2]); eb.y = pk2(y[0][3], y[1][3]);
        sYA[vp] = ea; sYB[vp] = eb;
    }
    __syncthreads();

    // ---- token loop: h = relu(Y@WW1 + rs*bb1 + b1); group-accumulate S@h ----
    int dA = t & 63, dB = dA + 64;
    int q  = t >> 6;
    u64 W0A = pk2(g_WW1[dA],     g_WW1[dA]);
    u64 W1A = pk2(g_WW1[128+dA], g_WW1[128+dA]);
    u64 W2A = pk2(g_WW1[256+dA], g_WW1[256+dA]);
    u64 W3A = pk2(g_WW1[384+dA], g_WW1[384+dA]);
    u64 BBA = pk2(g_bb1[dA],     g_bb1[dA]);
    u64 B1A = pk2(b1[dA],        b1[dA]);
    u64 W0B = pk2(g_WW1[dB],     g_WW1[dB]);
    u64 W1B = pk2(g_WW1[128+dB], g_WW1[128+dB]);
    u64 W2B = pk2(g_WW1[256+dB], g_WW1[256+dB]);
    u64 W3B = pk2(g_WW1[384+dB], g_WW1[384+dB]);
    u64 BBB = pk2(g_bb1[dB],     g_bb1[dB]);
    u64 B1B = pk2(b1[dB],        b1[dB]);
    u64 a01A = 0, a23A = 0, a01B = 0, a23B = 0;
    int vp0 = q*128;
    #pragma unroll 2
    for (int vp = vp0; vp < vp0+128; vp++) {
        ulonglong2 ya = sYA[vp], yb = sYB[vp];
        u64 rsp = sRSp[vp];
        u64 hA = fma2(ya.x, W0A, B1A);
        hA = fma2(ya.y, W1A, hA);
        hA = fma2(yb.x, W2A, hA);
        hA = fma2(yb.y, W3A, hA);
        hA = fma2(rsp,  BBA, hA);
        u64 hB = fma2(ya.x, W0B, B1B);
        hB = fma2(ya.y, W1B, hB);
        hB = fma2(yb.x, W2B, hB);
        hB = fma2(yb.y, W3B, hB);
        hB = fma2(rsp,  BBB, hB);
        float ae, ao, be, bo;
        upk2(hA, ae, ao); upk2(hB, be, bo);
        ae = fmaxf(ae, 0.f); ao = fmaxf(ao, 0.f);
        be = fmaxf(be, 0.f); bo = fmaxf(bo, 0.f);
        u64 hAe = pk2(ae, ae), hAo = pk2(ao, ao);
        u64 hBe = pk2(be, be), hBo = pk2(bo, bo);
        ulonglong2 s0 = sSI[2*vp], s1 = sSI[2*vp+1];
        a01A = fma2(s0.x, hAe, a01A); a23A = fma2(s0.y, hAe, a23A);
        a01A = fma2(s1.x, hAo, a01A); a23A = fma2(s1.y, hAo, a23A);
        a01B = fma2(s0.x, hBe, a01B); a23B = fma2(s0.y, hBe, a23B);
        a01B = fma2(s1.x, hBo, a01B); a23B = fma2(s1.y, hBo, a23B);
    }
    sAcc[t][0] = a01A; sAcc[t][1] = a23A; sAcc[t][2] = a01B; sAcc[t][3] = a23B;
    __syncthreads();

    // ---- reduce quarters, build gm ----
    if (t < 128) {
        int d = t, lane = d & 63, hi = d >> 6;
        float g0=0.f, g1=0.f, g2=0.f, g3=0.f;
        #pragma unroll
        for (int qq = 0; qq < 4; qq++) {
            float x0, x1;
            upk2(sAcc[qq*64+lane][hi*2+0], x0, x1); g0 += x0; g1 += x1;
            upk2(sAcc[qq*64+lane][hi*2+1], x0, x1); g2 += x0; g3 += x1;
        }
        ulonglong2 e;
        e.x = pk2(g0, g1); e.y = pk2(g2, g3);
        sU.gm[d] = e;
    }
    __syncthreads();

    // ---- epilogue: out = gm @ W2 + b2 + time ----
    if (t < 128) {
        int d = t;
        u64 o01 = 0, o23 = 0;
        #pragma unroll 4
        for (int c = 0; c < 128; c++) {
            ulonglong2 g = sU.gm[c];
            float w = __ldg(&W2[c*Dcst + d]);
            u64 ws = pk2(w, w);
            o01 = fma2(g.x, ws, o01);
            o23 = fma2(g.y, ws, o23);
        }
        float o0, o1, o2, o3;
        upk2(o01, o0, o1); upk2(o23, o2, o3);
        float base = tr + b2[d];
        long ob = ((long)(n*192 + tp*4))*Dcst + d;
        out[ob]     = o0 + base;
        out[ob+128] = o1 + base;
        out[ob+256] = o2 + base;
        out[ob+384] = o3 + base;
    }
}

// ---------------- launch ----------------
extern "C" void kernel_launch(void* const* d_in, const int* in_sizes, int n_in,
                              void* d_out, int out_size) {
    const float* x    = (const float*)d_in[0];
    const void*  xm   = d_in[1];
    const void*  ed   = d_in[2];
    const void*  ns   = d_in[3];
    const float* hemb = (const float*)d_in[4];
    const float* wemb = (const float*)d_in[5];
    const float* tcw  = (const float*)d_in[6];
    const float* tcb  = (const float*)d_in[7];
    const float* tvw  = (const float*)d_in[8];
    const float* tvb  = (const float*)d_in[9];
    const float* W1   = (const float*)d_in[10];
    const float* b1   = (const float*)d_in[11];
    const float* W2   = (const float*)d_in[12];
    const float* b2   = (const float*)d_in[13];
    float* out = (float*)d_out;

    kA<<<4,   1024>>>(ed, ns, tvw, tvb, W1);
    kB<<<452, 256>>>(ed, x);
    kC<<<NBcst, 256>>>(xm, hemb, wemb, tcw, tcb, b1, W2, b2, out);
}

// round 4
// speedup vs baseline: 9.4687x; 1.0562x over previous
#include <cuda_runtime.h>
#include <cuda_bf16.h>

#define Hcst   1024
#define Dcst   128
#define TPcst  48
#define NBcst  384
#define Ecst   16384
#define EHcst  17408
#define OUTHALF 196608

typedef unsigned long long u64;

// ---------------- device scratch ----------------
__device__ u64    g_Xh[NBcst*Hcst];      // 3.1 MB : bf16x4 taps per (b,node)
__device__ int    g_rowptr[Hcst+1];
__device__ int    g_cursor[Hcst];
__device__ float  g_deg[Hcst];
__device__ unsigned g_pk[EHcst];         // (bf16 coef)<<16 | col
__device__ float  g_rowsum[Hcst];
__device__ float  g_S[4*Hcst];
__device__ int    g_invgrp[Hcst];
__device__ float  g_WW1[4*Dcst];
__device__ float  g_bb1[Dcst];
__device__ float  g_time[NBcst*Dcst];

// ---------------- helpers ----------------
__device__ __forceinline__ u64 pk2(float lo, float hi) {
    u64 r; asm("mov.b64 %0,{%1,%2};" : "=l"(r) : "f"(lo), "f"(hi)); return r;
}
__device__ __forceinline__ void upk2(u64 v, float& lo, float& hi) {
    asm("mov.b64 {%0,%1},%2;" : "=f"(lo), "=f"(hi) : "l"(v));
}
__device__ __forceinline__ u64 fma2(u64 a, u64 b, u64 c) {
    u64 d; asm("fma.rn.f32x2 %0,%1,%2,%3;" : "=l"(d) : "l"(a), "l"(b), "l"(c)); return d;
}
__device__ __forceinline__ u64 pkbf4(float a, float b, float c, float d) {
    return (u64)__bfloat16_as_ushort(__float2bfloat16(a))
         | ((u64)__bfloat16_as_ushort(__float2bfloat16(b)) << 16)
         | ((u64)__bfloat16_as_ushort(__float2bfloat16(c)) << 32)
         | ((u64)__bfloat16_as_ushort(__float2bfloat16(d)) << 48);
}

// ================= k1 : all independent prep, chip-wide =================
__global__ void __launch_bounds__(1024) k1(const void* ed, const void* ns, const void* xm,
        const float* x, const float* hemb, const float* wemb,
        const float* tcw, const float* tcb,
        const float* tvw, const float* tvb, const float* W1, float* out) {
    int t = threadIdx.x, blk = blockIdx.x;
    if (blk == 0) {
        // edge count + exclusive scan
        __shared__ int sflag; __shared__ int cnt[Hcst]; __shared__ int wsum[32];
        if (t == 0) sflag = 1;
        __syncthreads();
        if (t < 64) { if (((const int*)ed)[2*t+1] != 0) atomicAnd(&sflag, 0); }
        cnt[t] = 1;
        __syncthreads();
        int f = sflag;
        for (int i = t; i < Ecst; i += 1024) {
            int d = f ? (int)((const long long*)ed)[2L*i+1] : ((const int*)ed)[2*i+1];
            atomicAdd(&cnt[d], 1);
        }
        __syncthreads();
        int c = cnt[t];
        int lane = t & 31, wid = t >> 5;
        int v = c;
        #pragma unroll
        for (int o = 1; o < 32; o <<= 1) { int uu = __shfl_up_sync(~0u, v, o); if (lane >= o) v += uu; }
        if (lane == 31) wsum[wid] = v;
        __syncthreads();
        if (wid == 0) {
            int w = wsum[lane];
            #pragma unroll
            for (int o = 1; o < 32; o <<= 1) { int uu = __shfl_up_sync(~0u, w, o); if (lane >= o) w += uu; }
            wsum[lane] = w;
        }
        __syncthreads();
        int incl = v + (wid > 0 ? wsum[wid-1] : 0);
        g_rowptr[t] = incl - c;
        g_cursor[t] = incl - c;
        g_deg[t]    = (float)c;
        if (t == 1023) g_rowptr[Hcst] = incl;
    } else if (blk == 1) {
        __shared__ int sflag;
        if (t == 0) sflag = 1;
        __syncthreads();
        if (t < 64) { if (((const int*)ns)[2*t+1] != 0) atomicAnd(&sflag, 0); }
        __syncthreads();
        int v = sflag ? (int)((const long long*)ns)[t] : ((const int*)ns)[t];
        g_invgrp[v] = t >> 8;
    } else if (blk == 2) {
        if (t < 512) {
            int k = t >> 7, e = t & 127;
            float acc = 0.f;
            for (int d = 0; d < Dcst; d++) acc += tvw[d*4 + k] * W1[d*Dcst + e];
            g_WW1[k*Dcst + e] = acc;
        } else if (t < 640) {
            int e = t - 512;
            float bsum = 0.f;
            for (int d = 0; d < Dcst; d++) bsum += tvb[d] * W1[d*Dcst + e];
            g_bb1[e] = bsum;
        }
    } else if (blk == 3) {
        for (int i = t; i < 4*Hcst; i += 1024) g_S[i] = 0.f;
        if (t < Hcst) g_rowsum[t] = 0.f;
    } else if (blk < 100) {
        // time embedding, 4 b's per block
        __shared__ int sflag;
        __shared__ float es[4][4][128];
        if (t == 0) sflag = 1;
        __syncthreads();
        if (t < 64) { if (((const int*)xm)[2*t+1] != 0) atomicAnd(&sflag, 0); }
        __syncthreads();
        int fm = sflag;
        int sub = t >> 8, tl = t & 255;
        int b = (blk - 4)*4 + sub, n = b / TPcst, tp = b % TPcst;
        for (int idx = tl; idx < 512; idx += 256) {
            int k = idx >> 7, c = idx & 127;
            long base = ((long)(n*192 + tp*4 + k))*2;
            int ih, iw;
            if (fm) { ih = (int)((const long long*)xm)[base+1]; iw = (int)((const long long*)xm)[base]; }
            else    { ih = ((const int*)xm)[base+1];             iw = ((const int*)xm)[base]; }
            es[sub][k][c] = hemb[ih*Dcst + c] + wemb[iw*Dcst + c];
        }
        __syncthreads();
        if (tl < 128) {
            int d = tl;
            float acc = tcb[d];
            const float4* w4 = (const float4*)(tcw + (long)d*512);
            #pragma unroll 4
            for (int c = 0; c < 128; c++) {
                float4 w = w4[c];
                acc += es[sub][0][c]*w.x + es[sub][1][c]*w.y + es[sub][2][c]*w.z + es[sub][3][c]*w.w;
            }
            g_time[b*Dcst + d] = acc;
            long ob = OUTHALF + ((long)(n*192 + tp*4))*Dcst + d;
            out[ob] = acc; out[ob+128] = acc; out[ob+256] = acc; out[ob+384] = acc;
        }
    } else {
        // X4 transpose -> packed bf16x4, 4 b's per block
        int sub = t >> 8, tl = t & 255;
        int b = (blk - 100)*4 + sub, n = b / TPcst, tp = b % TPcst;
        const float4* xr = (const float4*)(x + ((long)(n*192 + tp*4))*Hcst);
        float4 r0 = xr[tl], r1 = xr[256+tl], r2 = xr[512+tl], r3 = xr[768+tl];
        u64* dst = g_Xh + (long)b*Hcst + tl*4;
        dst[0] = pkbf4(r0.x, r1.x, r2.x, r3.x);
        dst[1] = pkbf4(r0.y, r1.y, r2.y, r3.y);
        dst[2] = pkbf4(r0.z, r1.z, r2.z, r3.z);
        dst[3] = pkbf4(r0.w, r1.w, r2.w, r3.w);
    }
}

// ================= k2 : CSR fill (+rowsum, +S) =================
__global__ void k2(const void* ed) {
    __shared__ int sflag;
    int t = threadIdx.x;
    if (t == 0) sflag = 1;
    __syncthreads();
    if (t < 64) { if (((const int*)ed)[2*t+1] != 0) atomicAnd(&sflag, 0); }
    __syncthreads();
    int f = sflag;
    int i = blockIdx.x*256 + t;
    if (i >= EHcst) return;
    int s, d;
    if (i < Ecst) {
        if (f) { s = (int)((const long long*)ed)[2L*i]; d = (int)((const long long*)ed)[2L*i+1]; }
        else   { s = ((const int*)ed)[2*i];             d = ((const int*)ed)[2*i+1]; }
    } else s = d = i - Ecst;
    float w = rsqrtf(g_deg[s]*g_deg[d]);
    int pos = atomicAdd(&g_cursor[d], 1);
    unsigned cb = (unsigned)__bfloat16_as_ushort(__float2bfloat16(w));
    g_pk[pos] = (unsigned)s | (cb << 16);
    atomicAdd(&g_rowsum[d], w);
    atomicAdd(&g_S[g_invgrp[d]*Hcst + s], w * (1.f/256.f));
}

// ================= k3 : per-b gather + token + epilogue =================
__global__ void __launch_bounds__(256, 3) k3(const float* b1, const float* W2,
                                             const float* b2, float* out) {
    __shared__ u64        sXh[Hcst];     // 8 KB  bf16x4 taps
    __shared__ ulonglong2 sYA[512];      // 8 KB
    __shared__ ulonglong2 sYB[512];      // 8 KB
    __shared__ ulonglong2 sSI[Hcst];     // 16 KB
    __shared__ u64        sRSp[512];     // 4 KB
    __shared__ u64        sAcc[256][4];  // 8 KB
    __shared__ ulonglong2 sGM[128];      // 2 KB

    int t = threadIdx.x, b = blockIdx.x;
    int n = b / TPcst, tp = b % TPcst;

    for (int i = t; i < Hcst; i += 256) {
        sXh[i] = g_Xh[(long)b*Hcst + i];
        ulonglong2 e;
        e.x = pk2(g_S[i],        g_S[Hcst+i]);
        e.y = pk2(g_S[2*Hcst+i], g_S[3*Hcst+i]);
        sSI[i] = e;
    }
    for (int vp = t; vp < 512; vp += 256)
        sRSp[vp] = pk2(g_rowsum[2*vp], g_rowsum[2*vp+1]);
    __syncthreads();

    // ---- gather from SMEM (bf16 taps) ----
    #pragma unroll
    for (int rep = 0; rep < 2; rep++) {
        int vp = t + rep*256;
        float y[2][4];
        #pragma unroll
        for (int e = 0; e < 2; e++) {
            int v = 2*vp + e;
            int j0 = g_rowptr[v], j1 = g_rowptr[v+1];
            float a0=0.f, a1=0.f, a2=0.f, a3=0.f;
            for (int j = j0; j < j1; j++) {
                unsigned p = __ldg(&g_pk[j]);
                float w = __uint_as_float(p & 0xFFFF0000u);
                u64 xv = sXh[p & 1023u];
                float t0 = __uint_as_float((unsigned)(xv & 0xFFFFu) << 16);
                float t1 = __uint_as_float((unsigned)xv & 0xFFFF0000u);
                float t2 = __uint_as_float((unsigned)((xv >> 32) & 0xFFFFu) << 16);
                float t3 = __uint_as_float((unsigned)(xv >> 48) << 16);
                a0 += w*t0; a1 += w*t1; a2 += w*t2; a3 += w*t3;
            }
            y[e][0]=a0; y[e][1]=a1; y[e][2]=a2; y[e][3]=a3;
        }
        ulonglong2 ea, eb;
        ea.x = pk2(y[0][0], y[1][0]); ea.y = pk2(y[0][1], y[1][1]);
        eb.x = pk2(y[0][2], y[1][2]); eb.y = pk2(y[0][3], y[1][3]);
        sYA[vp] = ea; sYB[vp] = eb;
    }
    __syncthreads();

    // ---- token loop ----
    int dA = t & 63, dB = dA + 64;
    int q  = t >> 6;
    u64 W0A = pk2(g_WW1[dA],     g_WW1[dA]);
    u64 W1A = pk2(g_WW1[128+dA], g_WW1[128+dA]);
    u64 W2A = pk2(g_WW1[256+dA], g_WW1[256+dA]);
    u64 W3A = pk2(g_WW1[384+dA], g_WW1[384+dA]);
    u64 BBA = pk2(g_bb1[dA],     g_bb1[dA]);
    u64 B1A = pk2(b1[dA],        b1[dA]);
    u64 W0B = pk2(g_WW1[dB],     g_WW1[dB]);
    u64 W1B = pk2(g_WW1[128+dB], g_WW1[128+dB]);
    u64 W2B = pk2(g_WW1[256+dB], g_WW1[256+dB]);
    u64 W3B = pk2(g_WW1[384+dB], g_WW1[384+dB]);
    u64 BBB = pk2(g_bb1[dB],     g_bb1[dB]);
    u64 B1B = pk2(b1[dB],        b1[dB]);
    u64 a01A = 0, a23A = 0, a01B = 0, a23B = 0;
    int vp0 = q*128;
    #pragma unroll 2
    for (int vp = vp0; vp < vp0+128; vp++) {
        ulonglong2 ya = sYA[vp], yb = sYB[vp];
        u64 rsp = sRSp[vp];
        u64 hA = fma2(ya.x, W0A, B1A);
        hA = fma2(ya.y, W1A, hA);
        hA = fma2(yb.x, W2A, hA);
        hA = fma2(yb.y, W3A, hA);
        hA = fma2(rsp,  BBA, hA);
        u64 hB = fma2(ya.x, W0B, B1B);
        hB = fma2(ya.y, W1B, hB);
        hB = fma2(yb.x, W2B, hB);
        hB = fma2(yb.y, W3B, hB);
        hB = fma2(rsp,  BBB, hB);
        float ae, ao, be, bo;
        upk2(hA, ae, ao); upk2(hB, be, bo);
        ae = fmaxf(ae, 0.f); ao = fmaxf(ao, 0.f);
        be = fmaxf(be, 0.f); bo = fmaxf(bo, 0.f);
        u64 hAe = pk2(ae, ae), hAo = pk2(ao, ao);
        u64 hBe = pk2(be, be), hBo = pk2(bo, bo);
        ulonglong2 s0 = sSI[2*vp], s1 = sSI[2*vp+1];
        a01A = fma2(s0.x, hAe, a01A); a23A = fma2(s0.y, hAe, a23A);
        a01A = fma2(s1.x, hAo, a01A); a23A = fma2(s1.y, hAo, a23A);
        a01B = fma2(s0.x, hBe, a01B); a23B = fma2(s0.y, hBe, a23B);
        a01B = fma2(s1.x, hBo, a01B); a23B = fma2(s1.y, hBo, a23B);
    }
    sAcc[t][0] = a01A; sAcc[t][1] = a23A; sAcc[t][2] = a01B; sAcc[t][3] = a23B;
    __syncthreads();

    // ---- reduce quarters -> group means (pre-W2) ----
    if (t < 128) {
        int d = t, lane = d & 63, hi = d >> 6;
        float g0=0.f, g1=0.f, g2=0.f, g3=0.f;
        #pragma unroll
        for (int qq = 0; qq < 4; qq++) {
            float x0, x1;
            upk2(sAcc[qq*64+lane][hi*2+0], x0, x1); g0 += x0; g1 += x1;
            upk2(sAcc[qq*64+lane][hi*2+1], x0, x1); g2 += x0; g3 += x1;
        }
        ulonglong2 e;
        e.x = pk2(g0, g1); e.y = pk2(g2, g3);
        sGM[d] = e;
    }
    __syncthreads();

    // ---- epilogue: out = gm @ W2 + b2 + time ----
    if (t < 128) {
        int d = t;
        u64 o01 = 0, o23 = 0;
        #pragma unroll 4
        for (int c = 0; c < 128; c++) {
            ulonglong2 g = sGM[c];
            float w = __ldg(&W2[c*Dcst + d]);
            u64 ws = pk2(w, w);
            o01 = fma2(g.x, ws, o01);
            o23 = fma2(g.y, ws, o23);
        }
        float o0, o1, o2, o3;
        upk2(o01, o0, o1); upk2(o23, o2, o3);
        float base = g_time[b*Dcst + d] + b2[d];
        long ob = ((long)(n*192 + tp*4))*Dcst + d;
        out[ob]     = o0 + base;
        out[ob+128] = o1 + base;
        out[ob+256] = o2 + base;
        out[ob+384] = o3 + base;
    }
}

// ---------------- launch ----------------
extern "C" void kernel_launch(void* const* d_in, const int* in_sizes, int n_in,
                              void* d_out, int out_size) {
    const float* x    = (const float*)d_in[0];
    const void*  xm   = d_in[1];
    const void*  ed   = d_in[2];
    const void*  ns   = d_in[3];
    const float* hemb = (const float*)d_in[4];
    const float* wemb = (const float*)d_in[5];
    const float* tcw  = (const float*)d_in[6];
    const float* tcb  = (const float*)d_in[7];
    const float* tvw  = (const float*)d_in[8];
    const float* tvb  = (const float*)d_in[9];
    const float* W1   = (const float*)d_in[10];
    const float* b1   = (const float*)d_in[11];
    const float* W2   = (const float*)d_in[12];
    const float* b2   = (const float*)d_in[13];
    float* out = (float*)d_out;

    k1<<<196, 1024>>>(ed, ns, xm, x, hemb, wemb, tcw, tcb, tvw, tvb, W1, out);
    k2<<<68, 256>>>(ed);
    k3<<<NBcst, 256>>>(b1, W2, b2, out);
}